// round 1
// baseline (speedup 1.0000x reference)
#include <cuda_runtime.h>

// Conditional encoding: 2-layer LSTM (B=1024, T=256, D=50, H=64) + MLP head.
// One persistent CTA per 8 batch rows; per-thread = one gate row (of 4H=256),
// weights in registers (packed f32x2), activations broadcast from SMEM.

#define BB   1024
#define TT   256
#define DD   50
#define HH   64
#define GG   256   // 4*H
#define BT   8     // batch rows per CTA
#define NCTA 128
#define NTHR 256

typedef unsigned long long u64;

__device__ __forceinline__ u64 pk2(float a, float b) {
    u64 r; asm("mov.b64 %0, {%1, %2};" : "=l"(r) : "f"(a), "f"(b)); return r;
}
__device__ __forceinline__ u64 ffma2(u64 a, u64 b, u64 c) {
    u64 d; asm("fma.rn.f32x2 %0, %1, %2, %3;" : "=l"(d) : "l"(a), "l"(b), "l"(c)); return d;
}
__device__ __forceinline__ float pairsum(u64 a) {
    float x, y; asm("mov.b64 {%0, %1}, %2;" : "=f"(x), "=f"(y) : "l"(a)); return x + y;
}
__device__ __forceinline__ float tanha(float x) {
    float y; asm("tanh.approx.f32 %0, %1;" : "=f"(y) : "f"(x)); return y;
}
__device__ __forceinline__ float siga(float x) {
    return fmaf(0.5f, tanha(0.5f * x), 0.5f);
}

__global__ void __launch_bounds__(NTHR, 1) cond_enc_kernel(
    const int*   __restrict__ s1,   const int*   __restrict__ s2,
    const int*   __restrict__ len1, const int*   __restrict__ len2,
    const float* __restrict__ emb,
    const float* __restrict__ Wih1, const float* __restrict__ Whh1,
    const float* __restrict__ bih1, const float* __restrict__ bhh1,
    const float* __restrict__ Wih2, const float* __restrict__ Whh2,
    const float* __restrict__ bih2, const float* __restrict__ bhh2,
    const float* __restrict__ Wl1,  const float* __restrict__ bl1,
    const float* __restrict__ Wl2,  const float* __restrict__ bl2,
    float* __restrict__ out)
{
    __shared__ int   toksh[BT][TT];                  // 8 KB
    __shared__ __align__(16) float xsh[2][BT][52];   // x padded 50 -> 52 (16B rows)
    __shared__ __align__(16) float hsh[BT][HH];
    __shared__ __align__(16) float csh[BT][HH];
    __shared__ float pre[BT][GG];                    // gate preactivations
    __shared__ float ghh[BT][HH];                    // gathered h
    __shared__ float ghc[BT][HH];                    // gathered c
    __shared__ int   glen[BT][HH];
    __shared__ float l1sh[BT][128];

    const int tid = threadIdx.x;
    const int b0  = blockIdx.x * BT;
    const int g   = tid;             // this thread's gate row (0..255)
    const int pr  = tid / 25;        // embedding prefetch: row   (tid < 200)
    const int pi  = tid - pr * 25;   // embedding prefetch: pair index

    u64   wreg[58];                  // [0..25] x-pairs (pair 25 = zero pad), [26..57] h-pairs
    float bias;

    for (int phase = 0; phase < 2; ++phase) {
        const int*   sent = phase ? s2   : s1;
        const int*   slen = phase ? len2 : len1;
        const float* Wih  = phase ? Wih2 : Wih1;
        const float* Whh  = phase ? Whh2 : Whh1;
        const float* bi   = phase ? bih2 : bih1;
        const float* bh   = phase ? bhh2 : bhh1;

        // ---- load this thread's gate-row weights into registers ----
        {
            const float* wp = Wih + g * DD;
            #pragma unroll
            for (int k = 0; k < 25; ++k) {
                float2 w = *(const float2*)(wp + 2 * k);
                wreg[k] = pk2(w.x, w.y);
            }
            wreg[25] = 0ULL;  // multiplies the x[50],x[51] zero pads
            const float4* hp = (const float4*)(Whh + g * HH);
            #pragma unroll
            for (int q = 0; q < 16; ++q) {
                float4 w = hp[q];
                wreg[26 + 2 * q] = pk2(w.x, w.y);
                wreg[27 + 2 * q] = pk2(w.z, w.w);
            }
            bias = bi[g] + bh[g];
        }

        // ---- stage tokens, gather indices, init h/c ----
        for (int idx = tid; idx < BT * TT; idx += NTHR) {
            int r = idx >> 8, t = idx & 255;
            toksh[r][t] = sent[(b0 + r) * TT + t];
        }
        for (int idx = tid; idx < BT * HH; idx += NTHR) {
            int r = idx >> 6, h = idx & 63;
            glen[r][h] = slen[(b0 + r) * HH + h];
            if (phase == 0) { hsh[r][h] = 0.f;       csh[r][h] = 0.f;       }
            else            { hsh[r][h] = ghh[r][h]; csh[r][h] = ghc[r][h]; }
        }
        if (tid < 32) xsh[(tid >> 4) & 1][(tid >> 1) & 7][50 + (tid & 1)] = 0.f;
        __syncthreads();

        // ---- x for t = 0 ----
        if (tid < 200) {
            int tok = toksh[pr][0];
            float2 v = *(const float2*)(emb + (long)tok * DD + 2 * pi);
            xsh[0][pr][2 * pi] = v.x; xsh[0][pr][2 * pi + 1] = v.y;
        }
        __syncthreads();

        // ================= recurrent time loop =================
        for (int t = 0; t < TT; ++t) {
            const int cur = t & 1, nxt = cur ^ 1;

            // prefetch x for t+1 into registers (latency hidden by dot phase)
            float2 pf;
            if (tid < 200) {
                int tn  = (t + 1 < TT) ? t + 1 : TT - 1;
                int tok = toksh[pr][tn];
                pf = *(const float2*)(emb + (long)tok * DD + 2 * pi);
            }

            // ---- dot phase: 8 rows x (50 + 64) MACs via packed f32x2 ----
            u64 a0[BT], a1[BT];
            #pragma unroll
            for (int b = 0; b < BT; ++b) { a0[b] = pk2(bias, 0.f); a1[b] = 0ULL; }
            #pragma unroll
            for (int kk = 0; kk < 13; ++kk) {
                #pragma unroll
                for (int b = 0; b < BT; ++b) {
                    ulonglong2 xv = *(const ulonglong2*)&xsh[cur][b][4 * kk];
                    a0[b] = ffma2(wreg[2 * kk],     xv.x, a0[b]);
                    a1[b] = ffma2(wreg[2 * kk + 1], xv.y, a1[b]);
                }
            }
            #pragma unroll
            for (int kk = 0; kk < 16; ++kk) {
                #pragma unroll
                for (int b = 0; b < BT; ++b) {
                    ulonglong2 hv = *(const ulonglong2*)&hsh[b][4 * kk];
                    a0[b] = ffma2(wreg[26 + 2 * kk], hv.x, a0[b]);
                    a1[b] = ffma2(wreg[27 + 2 * kk], hv.y, a1[b]);
                }
            }
            #pragma unroll
            for (int b = 0; b < BT; ++b) pre[b][g] = pairsum(a0[b]) + pairsum(a1[b]);
            __syncthreads();

            // commit prefetched x into the other buffer
            if (tid < 200) {
                xsh[nxt][pr][2 * pi]     = pf.x;
                xsh[nxt][pr][2 * pi + 1] = pf.y;
            }

            // ---- combine phase: each thread finalizes 2 (b, channel) pairs ----
            #pragma unroll
            for (int q = 0; q < 2; ++q) {
                int p  = tid + NTHR * q;
                int b  = p >> 6, hh = p & 63;
                float iv = pre[b][hh];
                float fv = pre[b][64 + hh];
                float gv = pre[b][128 + hh];
                float ov = pre[b][192 + hh];
                float c  = siga(fv) * csh[b][hh] + siga(iv) * tanha(gv);
                float h  = siga(ov) * tanha(c);
                csh[b][hh] = c; hsh[b][hh] = h;
                if (glen[b][hh] == t) { ghh[b][hh] = h; ghc[b][hh] = c; }
            }
            __syncthreads();
        }
    }

    // ================= MLP head =================
    #pragma unroll
    for (int q = 0; q < 4; ++q) {
        int p = tid + NTHR * q;
        int b = p >> 7, j = p & 127;
        float acc = bl1[j];
        const float* wr = Wl1 + j * HH;
        #pragma unroll
        for (int k = 0; k < HH; ++k) acc = fmaf(ghh[b][k], wr[k], acc);
        l1sh[b][j] = tanha(acc);
    }
    __syncthreads();
    if (tid < 32) {
        int b = tid >> 2, kk = tid & 3;
        float acc = bl2[kk];
        const float* wr = Wl2 + kk * 128;
        #pragma unroll
        for (int k = 0; k < 128; ++k) acc = fmaf(l1sh[b][k], wr[k], acc);
        out[(b0 + b) * 4 + kk] = acc;
    }
}

extern "C" void kernel_launch(void* const* d_in, const int* in_sizes, int n_in,
                              void* d_out, int out_size)
{
    const int*   s1   = (const int*)  d_in[0];
    const int*   s2   = (const int*)  d_in[1];
    const int*   len1 = (const int*)  d_in[2];
    const int*   len2 = (const int*)  d_in[3];
    // d_in[4], d_in[5] (s1_s, s2_s) unused by the reference model
    const float* emb  = (const float*)d_in[6];
    const float* Wih1 = (const float*)d_in[7];
    const float* Whh1 = (const float*)d_in[8];
    const float* bih1 = (const float*)d_in[9];
    const float* bhh1 = (const float*)d_in[10];
    const float* Wih2 = (const float*)d_in[11];
    const float* Whh2 = (const float*)d_in[12];
    const float* bih2 = (const float*)d_in[13];
    const float* bhh2 = (const float*)d_in[14];
    const float* Wl1  = (const float*)d_in[15];
    const float* bl1  = (const float*)d_in[16];
    const float* Wl2  = (const float*)d_in[17];
    const float* bl2  = (const float*)d_in[18];
    float* out = (float*)d_out;

    cond_enc_kernel<<<NCTA, NTHR>>>(s1, s2, len1, len2, emb,
                                    Wih1, Whh1, bih1, bhh1,
                                    Wih2, Whh2, bih2, bhh2,
                                    Wl1, bl1, Wl2, bl2, out);
}

// round 2
// speedup vs baseline: 1.3450x; 1.3450x over previous
#include <cuda_runtime.h>

// Conditional encoding: 2-layer LSTM (B=1024, T=256, D=50, H=64) + MLP head.
// Trick: x@Wih^T + bias is precomputed PER VOCAB ENTRY (32.8MB/layer table,
// L2-resident) so the serial recurrence only does the h@Whh^T half.
// Recurrent kernel: 256 CTAs x 4 batch rows, 2 CTAs/SM, thread = gate row,
// h-weights in packed f32x2 registers, h broadcast from SMEM.

#define BB   1024
#define TT   256
#define DD   50
#define HH   64
#define GG   256   // 4*H
#define VV   32004
#define BT   4     // batch rows per CTA
#define NCTA 256
#define NTHR 256

typedef unsigned long long u64;

__device__ float g_tab0[(long)VV * GG];   // layer-1 gate-x table (32.8 MB)
__device__ float g_tab1[(long)VV * GG];   // layer-2 gate-x table

__device__ __forceinline__ u64 pk2(float a, float b) {
    u64 r; asm("mov.b64 %0, {%1, %2};" : "=l"(r) : "f"(a), "f"(b)); return r;
}
__device__ __forceinline__ u64 ffma2(u64 a, u64 b, u64 c) {
    u64 d; asm("fma.rn.f32x2 %0, %1, %2, %3;" : "=l"(d) : "l"(a), "l"(b), "l"(c)); return d;
}
__device__ __forceinline__ float pairsum(u64 a) {
    float x, y; asm("mov.b64 {%0, %1}, %2;" : "=f"(x), "=f"(y) : "l"(a)); return x + y;
}
__device__ __forceinline__ float tanha(float x) {
    float y; asm("tanh.approx.f32 %0, %1;" : "=f"(y) : "f"(x)); return y;
}
__device__ __forceinline__ float siga(float x) {
    return fmaf(0.5f, tanha(0.5f * x), 0.5f);
}

// ---------------- precompute: tab[v][g] = emb[v] . Wih[g] + bih[g] + bhh[g] ----
__global__ void __launch_bounds__(256) precompute_kernel(
    const float* __restrict__ emb,
    const float* __restrict__ Wih,
    const float* __restrict__ bih,
    const float* __restrict__ bhh,
    int layer)
{
    float* tab = layer ? g_tab1 : g_tab0;
    __shared__ __align__(8) float xs[8][DD];
    const int tid = threadIdx.x;
    const int v0  = blockIdx.x * 8;

    // stage 8 embedding rows
    for (int idx = tid; idx < 8 * DD; idx += 256) {
        int r = idx / DD, k = idx - r * DD;
        int v = v0 + r;
        xs[r][k] = (v < VV) ? emb[(long)v * DD + k] : 0.f;
    }
    // this thread's gate row of Wih as packed pairs
    u64 w[25];
    const float* wp = Wih + tid * DD;
    #pragma unroll
    for (int k = 0; k < 25; ++k) {
        float2 t = *(const float2*)(wp + 2 * k);
        w[k] = pk2(t.x, t.y);
    }
    float bias = bih[tid] + bhh[tid];
    __syncthreads();

    #pragma unroll
    for (int r = 0; r < 8; ++r) {
        int v = v0 + r;
        if (v >= VV) break;
        u64 acc = pk2(bias, 0.f);
        #pragma unroll
        for (int k = 0; k < 25; ++k) {
            float2 xv = *(const float2*)&xs[r][2 * k];
            acc = ffma2(w[k], pk2(xv.x, xv.y), acc);
        }
        tab[(long)v * GG + tid] = pairsum(acc);
    }
}

// ---------------- recurrent kernel ----------------
__global__ void __launch_bounds__(NTHR, 2) cond_enc_kernel(
    const int*   __restrict__ s1,   const int*   __restrict__ s2,
    const int*   __restrict__ len1, const int*   __restrict__ len2,
    const float* __restrict__ Whh1,
    const float* __restrict__ Whh2,
    const float* __restrict__ Wl1,  const float* __restrict__ bl1,
    const float* __restrict__ Wl2,  const float* __restrict__ bl2,
    float* __restrict__ out)
{
    __shared__ int   toksh[BT][TT];                  // 4 KB
    __shared__ __align__(16) float hsh[BT][HH];
    __shared__ __align__(16) float csh[BT][HH];
    __shared__ float pre[BT][GG];                    // gate preactivations
    __shared__ float ghh[BT][HH];                    // gathered h
    __shared__ float ghc[BT][HH];                    // gathered c
    __shared__ int   glen[BT][HH];
    __shared__ float l1sh[BT][128];

    const int tid = threadIdx.x;
    const int b0  = blockIdx.x * BT;
    const int g   = tid;             // this thread's gate row (0..255)

    u64 wreg[32];                    // h-weight pairs for this gate row

    for (int phase = 0; phase < 2; ++phase) {
        const int*   sent = phase ? s2   : s1;
        const int*   slen = phase ? len2 : len1;
        const float* Whh  = phase ? Whh2 : Whh1;
        const float* tab  = phase ? g_tab1 : g_tab0;

        // ---- load h-weights into registers ----
        {
            const float4* hp = (const float4*)(Whh + g * HH);
            #pragma unroll
            for (int q = 0; q < 16; ++q) {
                float4 w = hp[q];
                wreg[2 * q]     = pk2(w.x, w.y);
                wreg[2 * q + 1] = pk2(w.z, w.w);
            }
        }

        // ---- stage tokens, gather indices, init h/c ----
        for (int idx = tid; idx < BT * TT; idx += NTHR) {
            int r = idx >> 8, t = idx & 255;
            toksh[r][t] = sent[(b0 + r) * TT + t];
        }
        {
            int r = tid >> 6, h = tid & 63;          // 256 threads = 4*64
            glen[r][h] = slen[(b0 + r) * HH + h];
            if (phase == 0) { hsh[r][h] = 0.f;       csh[r][h] = 0.f;       }
            else            { hsh[r][h] = ghh[r][h]; csh[r][h] = ghc[r][h]; }
        }
        __syncthreads();

        // gate-x values for t = 0
        float gx[BT];
        #pragma unroll
        for (int r = 0; r < BT; ++r)
            gx[r] = tab[(long)toksh[r][0] * GG + g];

        // ================= recurrent time loop =================
        for (int t = 0; t < TT; ++t) {
            // prefetch gate-x for t+1 (L2 hit ~250cyc, hidden by dot phase)
            float pf[BT];
            {
                int tn = (t + 1 < TT) ? t + 1 : TT - 1;
                #pragma unroll
                for (int r = 0; r < BT; ++r)
                    pf[r] = tab[(long)toksh[r][tn] * GG + g];
            }

            // ---- h-dot: 4 rows x 64 MACs via packed f32x2 ----
            u64 a0[BT], a1[BT];
            #pragma unroll
            for (int r = 0; r < BT; ++r) { a0[r] = pk2(gx[r], 0.f); a1[r] = 0ULL; }
            #pragma unroll
            for (int kk = 0; kk < 16; ++kk) {
                #pragma unroll
                for (int r = 0; r < BT; ++r) {
                    ulonglong2 hv = *(const ulonglong2*)&hsh[r][4 * kk];
                    a0[r] = ffma2(wreg[2 * kk],     hv.x, a0[r]);
                    a1[r] = ffma2(wreg[2 * kk + 1], hv.y, a1[r]);
                }
            }
            #pragma unroll
            for (int r = 0; r < BT; ++r) pre[r][g] = pairsum(a0[r]) + pairsum(a1[r]);
            #pragma unroll
            for (int r = 0; r < BT; ++r) gx[r] = pf[r];
            __syncthreads();

            // ---- combine: thread -> one (row, channel) ----
            {
                int r  = tid >> 6, hh = tid & 63;
                float iv = pre[r][hh];
                float fv = pre[r][64 + hh];
                float gv = pre[r][128 + hh];
                float ov = pre[r][192 + hh];
                float c  = siga(fv) * csh[r][hh] + siga(iv) * tanha(gv);
                float h  = siga(ov) * tanha(c);
                csh[r][hh] = c; hsh[r][hh] = h;
                if (glen[r][hh] == t) { ghh[r][hh] = h; ghc[r][hh] = c; }
            }
            __syncthreads();
        }
    }

    // ================= MLP head =================
    #pragma unroll
    for (int q = 0; q < 2; ++q) {
        int p = tid + NTHR * q;                      // 512 = 4 rows x 128
        int r = p >> 7, j = p & 127;
        float acc = bl1[j];
        const float* wr = Wl1 + j * HH;
        #pragma unroll
        for (int k = 0; k < HH; ++k) acc = fmaf(ghh[r][k], wr[k], acc);
        l1sh[r][j] = tanha(acc);
    }
    __syncthreads();
    if (tid < BT * 4) {
        int r = tid >> 2, kk = tid & 3;
        float acc = bl2[kk];
        const float* wr = Wl2 + kk * 128;
        #pragma unroll
        for (int k = 0; k < 128; ++k) acc = fmaf(l1sh[r][k], wr[k], acc);
        out[(b0 + r) * 4 + kk] = acc;
    }
}

extern "C" void kernel_launch(void* const* d_in, const int* in_sizes, int n_in,
                              void* d_out, int out_size)
{
    const int*   s1   = (const int*)  d_in[0];
    const int*   s2   = (const int*)  d_in[1];
    const int*   len1 = (const int*)  d_in[2];
    const int*   len2 = (const int*)  d_in[3];
    // d_in[4], d_in[5] (s1_s, s2_s) unused by the reference model
    const float* emb  = (const float*)d_in[6];
    const float* Wih1 = (const float*)d_in[7];
    const float* Whh1 = (const float*)d_in[8];
    const float* bih1 = (const float*)d_in[9];
    const float* bhh1 = (const float*)d_in[10];
    const float* Wih2 = (const float*)d_in[11];
    const float* Whh2 = (const float*)d_in[12];
    const float* bih2 = (const float*)d_in[13];
    const float* bhh2 = (const float*)d_in[14];
    const float* Wl1  = (const float*)d_in[15];
    const float* bl1  = (const float*)d_in[16];
    const float* Wl2  = (const float*)d_in[17];
    const float* bl2  = (const float*)d_in[18];
    float* out = (float*)d_out;

    const int nVB = (VV + 7) / 8;    // 4001 CTAs
    precompute_kernel<<<nVB, 256>>>(emb, Wih1, bih1, bhh1, 0);
    precompute_kernel<<<nVB, 256>>>(emb, Wih2, bih2, bhh2, 1);
    cond_enc_kernel<<<NCTA, NTHR>>>(s1, s2, len1, len2,
                                    Whh1, Whh2, Wl1, bl1, Wl2, bl2, out);
}

// round 3
// speedup vs baseline: 1.3778x; 1.0244x over previous
#include <cuda_runtime.h>

// Conditional encoding: 2-layer LSTM (B=1024, T=256, D=50, H=64) + MLP head.
// x@Wih^T+bias precomputed per vocab entry (GEMM, f32x2). Recurrence: 147 CTAs
// x 7 rows, 512 thr; warp = 8 channels x 4 gate types; shuffle-exchange gates,
// one combine per lane, c-state in regs, ONE barrier per step.

#define BB   1024
#define TT   256
#define DD   50
#define HH   64
#define GG   256   // 4*H
#define VV   32004
#define NR   7     // batch rows per recurrent CTA
#define RCTA 147   // 147*7 = 1029 >= 1024
#define RTHR 512
#define VB   501   // ceil(32004/64)

typedef unsigned long long u64;

__device__ float g_tab0[(long)VV * GG];   // layer-1 gate-x table (32.8 MB)
__device__ float g_tab1[(long)VV * GG];   // layer-2 gate-x table

__device__ __forceinline__ u64 pk2(float a, float b) {
    u64 r; asm("mov.b64 %0, {%1, %2};" : "=l"(r) : "f"(a), "f"(b)); return r;
}
__device__ __forceinline__ u64 ffma2(u64 a, u64 b, u64 c) {
    u64 d; asm("fma.rn.f32x2 %0, %1, %2, %3;" : "=l"(d) : "l"(a), "l"(b), "l"(c)); return d;
}
__device__ __forceinline__ float pairsum(u64 a) {
    float x, y; asm("mov.b64 {%0, %1}, %2;" : "=f"(x), "=f"(y) : "l"(a)); return x + y;
}
__device__ __forceinline__ float tanha(float x) {
    float y; asm("tanh.approx.f32 %0, %1;" : "=f"(y) : "f"(x)); return y;
}
__device__ __forceinline__ float siga(float x) {
    return fmaf(0.5f, tanha(0.5f * x), 0.5f);
}

// ---------------- precompute GEMM: tab[v][g] = emb[v].Wih[g] + bih[g]+bhh[g] ----
__global__ void __launch_bounds__(256, 2) precompute_kernel(
    const float* __restrict__ emb,
    const float* __restrict__ WihA, const float* __restrict__ biA, const float* __restrict__ bhA,
    const float* __restrict__ WihB, const float* __restrict__ biB, const float* __restrict__ bhB)
{
    const int layer = blockIdx.x >= VB;
    const int vb    = layer ? blockIdx.x - VB : blockIdx.x;
    const float* Wih = layer ? WihB : WihA;
    const float* bi  = layer ? biB  : biA;
    const float* bh  = layer ? bhB  : bhA;
    float* tab = layer ? g_tab1 : g_tab0;

    __shared__ float xs[64][DD];
    __shared__ __align__(8) float wsT[25][GG];
    __shared__ __align__(8) float bsh[GG];

    const int tid = threadIdx.x;
    const int v0  = vb * 64;

    for (int idx = tid; idx < 64 * DD; idx += 256) {
        int v = idx / DD, k = idx - v * DD;
        int vg = v0 + v;
        xs[v][k] = (vg < VV) ? emb[(long)vg * DD + k] : 0.f;
    }
    bsh[tid] = bi[tid] + bh[tid];
    __syncthreads();

    const int gg  = tid & 31;     // pair lane: this thread's g-pairs = 2*(gg+32j)
    const int vg8 = tid >> 5;     // v-group: rows vg8*8 .. +7

    u64 acc[8][4];
    #pragma unroll
    for (int j = 0; j < 4; ++j) {
        u64 bp = *(const u64*)&bsh[2 * (gg + 32 * j)];
        #pragma unroll
        for (int v = 0; v < 8; ++v) acc[v][j] = bp;
    }

    for (int kc = 0; kc < 2; ++kc) {
        __syncthreads();
        // stage transposed weight chunk: wsT[k][g] = Wih[g][kc*25+k]
        {
            const float* wp = Wih + (long)tid * DD + kc * 25;
            #pragma unroll
            for (int k = 0; k < 25; ++k) wsT[k][tid] = wp[k];
        }
        __syncthreads();
        #pragma unroll
        for (int k = 0; k < 25; ++k) {
            u64 wv[4];
            #pragma unroll
            for (int j = 0; j < 4; ++j)
                wv[j] = *(const u64*)&wsT[k][2 * (gg + 32 * j)];
            #pragma unroll
            for (int v = 0; v < 8; ++v) {
                float xv = xs[vg8 * 8 + v][kc * 25 + k];
                u64 xp = pk2(xv, xv);
                #pragma unroll
                for (int j = 0; j < 4; ++j) acc[v][j] = ffma2(wv[j], xp, acc[v][j]);
            }
        }
    }

    #pragma unroll
    for (int v = 0; v < 8; ++v) {
        int vg = v0 + vg8 * 8 + v;
        if (vg < VV) {
            #pragma unroll
            for (int j = 0; j < 4; ++j)
                *(u64*)(tab + (long)vg * GG + 2 * (gg + 32 * j)) = acc[v][j];
        }
    }
}

// ---------------- recurrent kernel ----------------
__global__ void __launch_bounds__(RTHR, 1) cond_enc_kernel(
    const int*   __restrict__ s1,   const int*   __restrict__ s2,
    const int*   __restrict__ len1, const int*   __restrict__ len2,
    const float* __restrict__ Whh1,
    const float* __restrict__ Whh2,
    const float* __restrict__ Wl1,  const float* __restrict__ bl1,
    const float* __restrict__ Wl2,  const float* __restrict__ bl2,
    float* __restrict__ out)
{
    __shared__ int   toksh[NR][TT];                       // 7 KB
    __shared__ __align__(16) float hsh[2][NR][HH];
    __shared__ float ghh[NR][HH];
    __shared__ float ghc[NR][HH];
    __shared__ float l1sh[NR][128];

    const int tid  = threadIdx.x;
    const int w    = tid >> 5, l = tid & 31;
    const int half = w >> 3;                 // 0: rows 0-3, 1: rows 4-6
    const int wl   = w & 7;
    const int ch   = wl * 8 + (l & 7);       // channel 0..63
    const int gt   = l >> 3;                 // gate type 0..3 (i,f,g,o)
    const int grow = gt * HH + ch;           // this lane's gate row
    const int nr   = half ? 3 : 4;
    const int r0   = half * 4;
    const int b0   = blockIdx.x * NR;
    const int rmy  = r0 + ((gt < nr) ? gt : nr - 1);  // my combine row (clamped)
    const bool act = (gt < nr);

    u64   wreg[32];       // Whh row for this gate
    float cmy;            // c-state for (rmy, ch)
    float mgh = 0.f, mgc = 0.f;
    int   glmy;

    for (int phase = 0; phase < 2; ++phase) {
        const int*   sent = phase ? s2   : s1;
        const int*   slen = phase ? len2 : len1;
        const float* Whh  = phase ? Whh2 : Whh1;
        const float* tab  = phase ? g_tab1 : g_tab0;

        // h-weights into registers
        {
            const float4* hp = (const float4*)(Whh + (long)grow * HH);
            #pragma unroll
            for (int q = 0; q < 16; ++q) {
                float4 wv = hp[q];
                wreg[2 * q]     = pk2(wv.x, wv.y);
                wreg[2 * q + 1] = pk2(wv.z, wv.w);
            }
        }
        // stage tokens
        for (int idx = tid; idx < NR * TT; idx += RTHR) {
            int r = idx >> 8, t = idx & 255;
            int b = b0 + r; if (b > BB - 1) b = BB - 1;
            toksh[r][t] = sent[b * TT + t];
        }
        // per-lane state init
        {
            int b = b0 + rmy; if (b > BB - 1) b = BB - 1;
            glmy = slen[b * HH + ch];
            cmy  = (phase == 0) ? 0.f : ghc[rmy][ch];
            if (act) hsh[0][rmy][ch] = (phase == 0) ? 0.f : ghh[rmy][ch];
        }
        __syncthreads();

        // gate-x for t=0
        float gx[4];
        #pragma unroll
        for (int rr = 0; rr < 4; ++rr) if (rr < nr)
            gx[rr] = tab[(long)toksh[r0 + rr][0] * GG + grow];

        // ================= time loop: ONE barrier per step =================
        for (int t = 0; t < TT; ++t) {
            const int cur = t & 1, nxt = cur ^ 1;

            // prefetch gate-x for t+1
            float pf[4];
            {
                int tn = (t + 1 < TT) ? t + 1 : TT - 1;
                #pragma unroll
                for (int rr = 0; rr < 4; ++rr) if (rr < nr)
                    pf[rr] = tab[(long)toksh[r0 + rr][tn] * GG + grow];
            }

            // dot: this gate row vs h of each batch row (broadcast LDS.128)
            u64 a[4];
            #pragma unroll
            for (int rr = 0; rr < 4; ++rr) if (rr < nr) a[rr] = pk2(gx[rr], 0.f);
            #pragma unroll
            for (int k = 0; k < 16; ++k) {
                #pragma unroll
                for (int rr = 0; rr < 4; ++rr) if (rr < nr) {
                    ulonglong2 hv = *(const ulonglong2*)&hsh[cur][r0 + rr][4 * k];
                    a[rr] = ffma2(wreg[2 * k],     hv.x, a[rr]);
                    a[rr] = ffma2(wreg[2 * k + 1], hv.y, a[rr]);
                }
            }

            // exchange gates within lane-group {l, l^8, l^16, l^24}; keep row gt
            float miv = 0.f, mfv = 0.f, mgv = 0.f, mov_ = 0.f;
            #pragma unroll
            for (int rr = 0; rr < 4; ++rr) if (rr < nr) {
                float av = pairsum(a[rr]);
                float p  = __shfl_xor_sync(0xffffffffu, av, 8);
                float lo = (gt & 1) ? p  : av;
                float hi = (gt & 1) ? av : p;
                float qlo = __shfl_xor_sync(0xffffffffu, lo, 16);
                float qhi = __shfl_xor_sync(0xffffffffu, hi, 16);
                float iv = (gt < 2) ? lo  : qlo;
                float fv = (gt < 2) ? hi  : qhi;
                float gv = (gt < 2) ? qlo : lo;
                float ov = (gt < 2) ? qhi : hi;
                bool mine = (gt == rr);
                miv  = mine ? iv : miv;
                mfv  = mine ? fv : mfv;
                mgv  = mine ? gv : mgv;
                mov_ = mine ? ov : mov_;
                gx[rr] = pf[rr];
            }

            // one combine per lane (row rmy, channel ch)
            {
                float cn = siga(mfv) * cmy + siga(miv) * tanha(mgv);
                float hn = siga(mov_) * tanha(cn);
                cmy = cn;
                if (glmy == t) { mgh = hn; mgc = cn; }
                if (act) hsh[nxt][rmy][ch] = hn;
            }
            __syncthreads();
        }

        // publish gathered h/c for next phase / head
        if (act) { ghh[rmy][ch] = mgh; ghc[rmy][ch] = mgc; }
        __syncthreads();
    }

    // ================= MLP head =================
    for (int p = tid; p < NR * 128; p += RTHR) {
        int r = p >> 7, j = p & 127;
        float acc = bl1[j];
        const float* wr = Wl1 + j * HH;
        #pragma unroll
        for (int k = 0; k < HH; ++k) acc = fmaf(ghh[r][k], wr[k], acc);
        l1sh[r][j] = tanha(acc);
    }
    __syncthreads();
    if (tid < NR * 4) {
        int r = tid >> 2, kk = tid & 3;
        int b = b0 + r;
        if (b < BB) {
            float acc = bl2[kk];
            const float* wr = Wl2 + kk * 128;
            #pragma unroll
            for (int k = 0; k < 128; ++k) acc = fmaf(l1sh[r][k], wr[k], acc);
            out[b * 4 + kk] = acc;
        }
    }
}

extern "C" void kernel_launch(void* const* d_in, const int* in_sizes, int n_in,
                              void* d_out, int out_size)
{
    const int*   s1   = (const int*)  d_in[0];
    const int*   s2   = (const int*)  d_in[1];
    const int*   len1 = (const int*)  d_in[2];
    const int*   len2 = (const int*)  d_in[3];
    // d_in[4], d_in[5] (s1_s, s2_s) unused by the reference model
    const float* emb  = (const float*)d_in[6];
    const float* Wih1 = (const float*)d_in[7];
    const float* Whh1 = (const float*)d_in[8];
    const float* bih1 = (const float*)d_in[9];
    const float* bhh1 = (const float*)d_in[10];
    const float* Wih2 = (const float*)d_in[11];
    const float* Whh2 = (const float*)d_in[12];
    const float* bih2 = (const float*)d_in[13];
    const float* bhh2 = (const float*)d_in[14];
    const float* Wl1  = (const float*)d_in[15];
    const float* bl1  = (const float*)d_in[16];
    const float* Wl2  = (const float*)d_in[17];
    const float* bl2  = (const float*)d_in[18];
    float* out = (float*)d_out;

    precompute_kernel<<<2 * VB, 256>>>(emb, Wih1, bih1, bhh1, Wih2, bih2, bhh2);
    cond_enc_kernel<<<RCTA, RTHR>>>(s1, s2, len1, len2,
                                    Whh1, Whh2, Wl1, bl1, Wl2, bl2, out);
}

// round 4
// speedup vs baseline: 1.5707x; 1.1400x over previous
#include <cuda_runtime.h>

// Conditional encoding: 2-layer LSTM (B=1024, T=256, D=50, H=64) + MLP head.
// x@Wih^T+bias precomputed per vocab entry (f32x2 GEMM -> 32.8MB L2 table).
// Recurrence: 256 CTAs x 4 rows, 2 CTAs/SM, thread = gate row, h-weights in
// packed f32x2 regs, compile-time double-buffered h (unroll-2 time loop),
// combine state in registers.

#define BB   1024
#define TT   256
#define DD   50
#define HH   64
#define GG   256   // 4*H
#define VV   32004
#define BT   4     // batch rows per recurrent CTA
#define NCTA 256
#define NTHR 256
#define VB   501   // ceil(32004/64)

typedef unsigned long long u64;

__device__ float g_tab0[(long)VV * GG];   // layer-1 gate-x table (32.8 MB)
__device__ float g_tab1[(long)VV * GG];   // layer-2 gate-x table

__device__ __forceinline__ u64 pk2(float a, float b) {
    u64 r; asm("mov.b64 %0, {%1, %2};" : "=l"(r) : "f"(a), "f"(b)); return r;
}
__device__ __forceinline__ u64 ffma2(u64 a, u64 b, u64 c) {
    u64 d; asm("fma.rn.f32x2 %0, %1, %2, %3;" : "=l"(d) : "l"(a), "l"(b), "l"(c)); return d;
}
__device__ __forceinline__ float pairsum(u64 a) {
    float x, y; asm("mov.b64 {%0, %1}, %2;" : "=f"(x), "=f"(y) : "l"(a)); return x + y;
}
__device__ __forceinline__ float tanha(float x) {
    float y; asm("tanh.approx.f32 %0, %1;" : "=f"(y) : "f"(x)); return y;
}
__device__ __forceinline__ float siga(float x) {
    return fmaf(0.5f, tanha(0.5f * x), 0.5f);
}

// ---------------- precompute GEMM: tab[v][g] = emb[v].Wih[g] + bih[g]+bhh[g] ----
__global__ void __launch_bounds__(256, 2) precompute_kernel(
    const float* __restrict__ emb,
    const float* __restrict__ WihA, const float* __restrict__ biA, const float* __restrict__ bhA,
    const float* __restrict__ WihB, const float* __restrict__ biB, const float* __restrict__ bhB)
{
    const int layer = blockIdx.x >= VB;
    const int vb    = layer ? blockIdx.x - VB : blockIdx.x;
    const float* Wih = layer ? WihB : WihA;
    const float* bi  = layer ? biB  : biA;
    const float* bh  = layer ? bhB  : bhA;
    float* tab = layer ? g_tab1 : g_tab0;

    __shared__ float xs[64][DD];
    __shared__ __align__(8) float wsT[25][GG];
    __shared__ __align__(8) float bsh[GG];

    const int tid = threadIdx.x;
    const int v0  = vb * 64;

    for (int idx = tid; idx < 64 * DD; idx += 256) {
        int v = idx / DD, k = idx - v * DD;
        int vg = v0 + v;
        xs[v][k] = (vg < VV) ? emb[(long)vg * DD + k] : 0.f;
    }
    bsh[tid] = bi[tid] + bh[tid];
    __syncthreads();

    const int gg  = tid & 31;
    const int vg8 = tid >> 5;

    u64 acc[8][4];
    #pragma unroll
    for (int j = 0; j < 4; ++j) {
        u64 bp = *(const u64*)&bsh[2 * (gg + 32 * j)];
        #pragma unroll
        for (int v = 0; v < 8; ++v) acc[v][j] = bp;
    }

    for (int kc = 0; kc < 2; ++kc) {
        __syncthreads();
        {
            const float* wp = Wih + (long)tid * DD + kc * 25;
            #pragma unroll
            for (int k = 0; k < 25; ++k) wsT[k][tid] = wp[k];
        }
        __syncthreads();
        #pragma unroll
        for (int k = 0; k < 25; ++k) {
            u64 wv[4];
            #pragma unroll
            for (int j = 0; j < 4; ++j)
                wv[j] = *(const u64*)&wsT[k][2 * (gg + 32 * j)];
            #pragma unroll
            for (int v = 0; v < 8; ++v) {
                float xv = xs[vg8 * 8 + v][kc * 25 + k];
                u64 xp = pk2(xv, xv);
                #pragma unroll
                for (int j = 0; j < 4; ++j) acc[v][j] = ffma2(wv[j], xp, acc[v][j]);
            }
        }
    }

    #pragma unroll
    for (int v = 0; v < 8; ++v) {
        int vg = v0 + vg8 * 8 + v;
        if (vg < VV) {
            #pragma unroll
            for (int j = 0; j < 4; ++j)
                *(u64*)(tab + (long)vg * GG + 2 * (gg + 32 * j)) = acc[v][j];
        }
    }
}

// ---------------- recurrent kernel ----------------
__global__ void __launch_bounds__(NTHR, 2) cond_enc_kernel(
    const int*   __restrict__ s1,   const int*   __restrict__ s2,
    const int*   __restrict__ len1, const int*   __restrict__ len2,
    const float* __restrict__ Whh1,
    const float* __restrict__ Whh2,
    const float* __restrict__ Wl1,  const float* __restrict__ bl1,
    const float* __restrict__ Wl2,  const float* __restrict__ bl2,
    float* __restrict__ out)
{
    __shared__ int   toksh[BT][TT];                      // 4 KB
    __shared__ __align__(16) float hA[BT][HH];           // h double buffers
    __shared__ __align__(16) float hB[BT][HH];
    __shared__ float pre[BT][GG];                        // gate preactivations
    __shared__ float ghh[BT][HH];
    __shared__ float ghc[BT][HH];
    __shared__ float l1sh[BT][128];

    const int tid = threadIdx.x;
    const int b0  = blockIdx.x * BT;
    const int g   = tid;                 // this thread's gate row (0..255)
    const int cr  = tid >> 6;            // combine row
    const int chh = tid & 63;            // combine channel

    u64   wreg[32];                      // h-weight pairs for this gate row
    float gx[BT], pf[BT];
    float cmy;                           // c-state (register)
    float mgh = 0.f, mgc = 0.f;
    int   glmy;

    for (int phase = 0; phase < 2; ++phase) {
        const int*   sent = phase ? s2   : s1;
        const int*   slen = phase ? len2 : len1;
        const float* Whh  = phase ? Whh2 : Whh1;
        const float* tab  = phase ? g_tab1 : g_tab0;

        // ---- h-weights into registers ----
        {
            const float4* hp = (const float4*)(Whh + (long)g * HH);
            #pragma unroll
            for (int q = 0; q < 16; ++q) {
                float4 w = hp[q];
                wreg[2 * q]     = pk2(w.x, w.y);
                wreg[2 * q + 1] = pk2(w.z, w.w);
            }
        }
        // ---- stage tokens; init per-thread combine state; init hA ----
        for (int idx = tid; idx < BT * TT; idx += NTHR) {
            int r = idx >> 8, t = idx & 255;
            toksh[r][t] = sent[(b0 + r) * TT + t];
        }
        glmy = slen[(b0 + cr) * HH + chh];
        cmy  = (phase == 0) ? 0.f : ghc[cr][chh];
        hA[cr][chh] = (phase == 0) ? 0.f : ghh[cr][chh];
        __syncthreads();

        // gate-x for t=0
        #pragma unroll
        for (int r = 0; r < BT; ++r)
            gx[r] = __ldg(&tab[(long)toksh[r][0] * GG + g]);

        // ================= time loop, unrolled x2 (compile-time buffers) ====
        #pragma unroll 1
        for (int t = 0; t < TT; t += 2) {
            // ---------- step even: read hA, write hB ----------
            {
                const int tn = t + 1;
                #pragma unroll
                for (int r = 0; r < BT; ++r)
                    pf[r] = __ldg(&tab[(long)toksh[r][tn] * GG + g]);

                u64 a0[BT], a1[BT];
                #pragma unroll
                for (int r = 0; r < BT; ++r) { a0[r] = pk2(gx[r], 0.f); a1[r] = 0ULL; }
                #pragma unroll
                for (int k = 0; k < 16; ++k) {
                    #pragma unroll
                    for (int r = 0; r < BT; ++r) {
                        ulonglong2 hv = *(const ulonglong2*)&hA[r][4 * k];
                        a0[r] = ffma2(wreg[2 * k],     hv.x, a0[r]);
                        a1[r] = ffma2(wreg[2 * k + 1], hv.y, a1[r]);
                    }
                }
                #pragma unroll
                for (int r = 0; r < BT; ++r) {
                    pre[r][g] = pairsum(a0[r]) + pairsum(a1[r]);
                    gx[r] = pf[r];
                }
                __syncthreads();

                float iv = pre[cr][chh];
                float fv = pre[cr][64 + chh];
                float gv = pre[cr][128 + chh];
                float ov = pre[cr][192 + chh];
                float cn = siga(fv) * cmy + siga(iv) * tanha(gv);
                float hn = siga(ov) * tanha(cn);
                cmy = cn;
                if (glmy == t) { mgh = hn; mgc = cn; }
                hB[cr][chh] = hn;
                __syncthreads();
            }
            // ---------- step odd: read hB, write hA ----------
            {
                const int tn = (t + 2 < TT) ? t + 2 : TT - 1;
                #pragma unroll
                for (int r = 0; r < BT; ++r)
                    pf[r] = __ldg(&tab[(long)toksh[r][tn] * GG + g]);

                u64 a0[BT], a1[BT];
                #pragma unroll
                for (int r = 0; r < BT; ++r) { a0[r] = pk2(gx[r], 0.f); a1[r] = 0ULL; }
                #pragma unroll
                for (int k = 0; k < 16; ++k) {
                    #pragma unroll
                    for (int r = 0; r < BT; ++r) {
                        ulonglong2 hv = *(const ulonglong2*)&hB[r][4 * k];
                        a0[r] = ffma2(wreg[2 * k],     hv.x, a0[r]);
                        a1[r] = ffma2(wreg[2 * k + 1], hv.y, a1[r]);
                    }
                }
                #pragma unroll
                for (int r = 0; r < BT; ++r) {
                    pre[r][g] = pairsum(a0[r]) + pairsum(a1[r]);
                    gx[r] = pf[r];
                }
                __syncthreads();

                float iv = pre[cr][chh];
                float fv = pre[cr][64 + chh];
                float gv = pre[cr][128 + chh];
                float ov = pre[cr][192 + chh];
                float cn = siga(fv) * cmy + siga(iv) * tanha(gv);
                float hn = siga(ov) * tanha(cn);
                cmy = cn;
                if (glmy == t + 1) { mgh = hn; mgc = cn; }
                hA[cr][chh] = hn;
                __syncthreads();
            }
        }

        // publish gathered h/c for next phase / head
        ghh[cr][chh] = mgh;
        ghc[cr][chh] = mgc;
        __syncthreads();
    }

    // ================= MLP head =================
    #pragma unroll
    for (int q = 0; q < 2; ++q) {
        int p = tid + NTHR * q;                      // 512 = 4 rows x 128
        int r = p >> 7, j = p & 127;
        float acc = bl1[j];
        const float* wr = Wl1 + j * HH;
        #pragma unroll
        for (int k = 0; k < HH; ++k) acc = fmaf(ghh[r][k], wr[k], acc);
        l1sh[r][j] = tanha(acc);
    }
    __syncthreads();
    if (tid < BT * 4) {
        int r = tid >> 2, kk = tid & 3;
        float acc = bl2[kk];
        const float* wr = Wl2 + kk * 128;
        #pragma unroll
        for (int k = 0; k < 128; ++k) acc = fmaf(l1sh[r][k], wr[k], acc);
        out[(b0 + r) * 4 + kk] = acc;
    }
}

extern "C" void kernel_launch(void* const* d_in, const int* in_sizes, int n_in,
                              void* d_out, int out_size)
{
    const int*   s1   = (const int*)  d_in[0];
    const int*   s2   = (const int*)  d_in[1];
    const int*   len1 = (const int*)  d_in[2];
    const int*   len2 = (const int*)  d_in[3];
    // d_in[4], d_in[5] (s1_s, s2_s) unused by the reference model
    const float* emb  = (const float*)d_in[6];
    const float* Wih1 = (const float*)d_in[7];
    const float* Whh1 = (const float*)d_in[8];
    const float* bih1 = (const float*)d_in[9];
    const float* bhh1 = (const float*)d_in[10];
    const float* Wih2 = (const float*)d_in[11];
    const float* Whh2 = (const float*)d_in[12];
    const float* bih2 = (const float*)d_in[13];
    const float* bhh2 = (const float*)d_in[14];
    const float* Wl1  = (const float*)d_in[15];
    const float* bl1  = (const float*)d_in[16];
    const float* Wl2  = (const float*)d_in[17];
    const float* bl2  = (const float*)d_in[18];
    float* out = (float*)d_out;

    precompute_kernel<<<2 * VB, 256>>>(emb, Wih1, bih1, bhh1, Wih2, bih2, bhh2);
    cond_enc_kernel<<<NCTA, NTHR>>>(s1, s2, len1, len2,
                                    Whh1, Whh2, Wl1, bl1, Wl2, bl2, out);
}